// round 15
// baseline (speedup 1.0000x reference)
#include <cuda_runtime.h>
#include <cuda_fp16.h>
#include <cstdint>

#define NN 32768
#define NE 262144
#define HC 512
#define KPAD 128
#define NOUT2 1024

// h0 GEMM tiling (BK=32, compensated 3-term)
#define BM 128
#define BN 128
#define BK 32
#define ROWB 80                       // 32 halfs + 16B pad
#define PLANE_B (128 * ROWB)          // 10240

// PQ GEMM tiling (BK=64, single-term fp16)
#define ROWB2 144                     // 64 halfs + 16B pad
#define PLANE2 (128 * ROWB2)          // 18432
#define STG2 (2 * PLANE2)             // 36864 (A,B)
#define SMEM2 (2 * STG2)              // 73728

// ---------------- scratch (static device globals) ---------------------------
__device__ float g_h[NN * HC];
__device__ float g_h2[NN * HC];
__device__ __half g_PQh[NN * NOUT2];  // [P | Q] per row, fp16 (64MB, L2-resident)
__device__ float g_score[NE * 8];     // alpha (+ rare overflow scratch)
__device__ int   g_deg[NN];
__device__ int   g_cursor[NN];
__device__ int   g_start[NN + 1];
__device__ int   g_eidx[NE];

__device__ __half g_x1[NN * KPAD];    // x hi/lo planes (h0 is fully compensated)
__device__ __half g_x2[NN * KPAD];
__device__ __half g_hA1[NN * HC];     // fp16 h plane (PQ GEMM input)
__device__ __half g_WnT1[HC * KPAD];
__device__ __half g_WnT2[HC * KPAD];
__device__ __half g_Wc1[NOUT2 * HC];  // combined Wa^T hi plane

// ---------------- ptx helpers -----------------------------------------------
__device__ __forceinline__ uint32_t smem_u32(const void* p) {
    uint32_t a;
    asm("{ .reg .u64 t; cvta.to.shared.u64 t, %1; cvt.u32.u64 %0, t; }" : "=r"(a) : "l"(p));
    return a;
}
__device__ __forceinline__ void cp16(uint32_t dst, const void* src) {
    asm volatile("cp.async.cg.shared.global [%0], [%1], 16;" :: "r"(dst), "l"(src) : "memory");
}
__device__ __forceinline__ void ldm4(uint32_t* r, uint32_t addr) {
    asm volatile("ldmatrix.sync.aligned.m8n8.x4.shared.b16 {%0,%1,%2,%3}, [%4];"
                 : "=r"(r[0]), "=r"(r[1]), "=r"(r[2]), "=r"(r[3]) : "r"(addr));
}
__device__ __forceinline__ void mma16816(float* c, const uint32_t* a, const uint32_t* b) {
    asm volatile(
        "mma.sync.aligned.m16n8k16.row.col.f32.f16.f16.f32 "
        "{%0,%1,%2,%3}, {%4,%5,%6,%7}, {%8,%9}, {%0,%1,%2,%3};"
        : "+f"(c[0]), "+f"(c[1]), "+f"(c[2]), "+f"(c[3])
        : "r"(a[0]), "r"(a[1]), "r"(a[2]), "r"(a[3]), "r"(b[0]), "r"(b[1]));
}
__device__ __forceinline__ void split16(float v, __half& hi, __half& lo) {
    hi = __float2half_rn(v);
    lo = __float2half_rn(v - __half2float(hi));
}

// ================= h0 GEMM: compensated 3-term, BK=32 ========================
__device__ __forceinline__ void ld_chunk4(uint32_t sbase,
                                          const __half* A1, const __half* A2,
                                          const __half* B1, const __half* B2,
                                          int bm0, int bn0, int K, int k0, int tid) {
#pragma unroll
    for (int p = tid; p < 512; p += 256) {
        int row = p >> 2, seg = p & 3;
        uint32_t soff = (uint32_t)(row * ROWB + seg * 16);
        size_t ga = ((size_t)(bm0 + row) * K + k0 + seg * 8) * 2;
        size_t gb = ((size_t)(bn0 + row) * K + k0 + seg * 8) * 2;
        cp16(sbase + soff,               (const char*)A1 + ga);
        cp16(sbase + PLANE_B + soff,     (const char*)A2 + ga);
        cp16(sbase + 2 * PLANE_B + soff, (const char*)B1 + gb);
        cp16(sbase + 3 * PLANE_B + soff, (const char*)B2 + gb);
    }
}

__global__ __launch_bounds__(256, 2)
void gemm_h0_k(const __half* __restrict__ A1, const __half* __restrict__ A2,
               const __half* __restrict__ B1, const __half* __restrict__ B2,
               const float* __restrict__ bias, float* __restrict__ Cf,
               __half* __restrict__ Ch, int K, int NOUT) {
    constexpr uint32_t STG_T = 4 * PLANE_B;
    extern __shared__ char smem[];
    const uint32_t sb = smem_u32(smem);
    const int tid = threadIdx.x;
    const int wid = tid >> 5, lane = tid & 31;
    const int warp_m = wid & 3;
    const int warp_n = wid >> 2;
    const int bm0 = blockIdx.y * BM;
    const int bn0 = blockIdx.x * BN;

    float acc[2][8][4];
#pragma unroll
    for (int i = 0; i < 2; i++)
#pragma unroll
        for (int j = 0; j < 8; j++)
#pragma unroll
            for (int k = 0; k < 4; k++) acc[i][j][k] = 0.f;

    const int nch = K / BK;

    ld_chunk4(sb, A1, A2, B1, B2, bm0, bn0, K, 0, tid);
    asm volatile("cp.async.commit_group;" ::: "memory");

    const uint32_t a_row = (uint32_t)(warp_m * 32 + (lane & 15));
    const uint32_t a_k8  = (uint32_t)((lane >> 4) * 8);
    const uint32_t b_row = (uint32_t)(warp_n * 64 + (lane & 7) + ((lane >> 4) << 3));
    const uint32_t b_k8  = (uint32_t)(((lane >> 3) & 1) * 8);

    int stage = 0;
    for (int c = 0; c < nch; ++c) {
        if (c + 1 < nch) {
            ld_chunk4(sb + (stage ^ 1) * STG_T, A1, A2, B1, B2, bm0, bn0, K,
                      (c + 1) * BK, tid);
            asm volatile("cp.async.commit_group;" ::: "memory");
            asm volatile("cp.async.wait_group 1;" ::: "memory");
        } else {
            asm volatile("cp.async.wait_group 0;" ::: "memory");
        }
        __syncthreads();

        const uint32_t s = sb + stage * STG_T;
        const uint32_t sA1 = s, sA2 = s + PLANE_B;
        const uint32_t sB1 = s + 2 * PLANE_B, sB2 = s + 3 * PLANE_B;

#pragma unroll
        for (int ks = 0; ks < 2; ks++) {
            const uint32_t aoff = a_row * ROWB + (ks * 16 + a_k8) * 2;
            const uint32_t boff = b_row * ROWB + (ks * 16 + b_k8) * 2;

            uint32_t a1[2][4], b1[8][2];
            ldm4(a1[0], sA1 + aoff);
            ldm4(a1[1], sA1 + aoff + 16 * ROWB);
#pragma unroll
            for (int bt = 0; bt < 4; bt++) {
                uint32_t r[4];
                ldm4(r, sB1 + boff + bt * 16 * ROWB);
                b1[2 * bt][0] = r[0]; b1[2 * bt][1] = r[1];
                b1[2 * bt + 1][0] = r[2]; b1[2 * bt + 1][1] = r[3];
            }
#pragma unroll
            for (int mt = 0; mt < 2; mt++)
#pragma unroll
                for (int nt = 0; nt < 8; nt++)
                    mma16816(acc[mt][nt], a1[mt], b1[nt]);

            {   // A2 x B1
                uint32_t a2[2][4];
                ldm4(a2[0], sA2 + aoff);
                ldm4(a2[1], sA2 + aoff + 16 * ROWB);
#pragma unroll
                for (int mt = 0; mt < 2; mt++)
#pragma unroll
                    for (int nt = 0; nt < 8; nt++)
                        mma16816(acc[mt][nt], a2[mt], b1[nt]);
            }
            {   // A1 x B2
                uint32_t b2[8][2];
#pragma unroll
                for (int bt = 0; bt < 4; bt++) {
                    uint32_t r[4];
                    ldm4(r, sB2 + boff + bt * 16 * ROWB);
                    b2[2 * bt][0] = r[0]; b2[2 * bt][1] = r[1];
                    b2[2 * bt + 1][0] = r[2]; b2[2 * bt + 1][1] = r[3];
                }
#pragma unroll
                for (int mt = 0; mt < 2; mt++)
#pragma unroll
                    for (int nt = 0; nt < 8; nt++)
                        mma16816(acc[mt][nt], a1[mt], b2[nt]);
            }
        }
        __syncthreads();
        stage ^= 1;
    }

    const int r0 = bm0 + warp_m * 32 + (lane >> 2);
    const int c0 = bn0 + warp_n * 64 + (lane & 3) * 2;
#pragma unroll
    for (int mt = 0; mt < 2; mt++) {
#pragma unroll
        for (int nt = 0; nt < 8; nt++) {
            int col = c0 + nt * 8;
            float b0 = bias[col], b1v = bias[col + 1];
            int row = r0 + mt * 16;
            float v00 = acc[mt][nt][0] + b0, v01 = acc[mt][nt][1] + b1v;
            float v10 = acc[mt][nt][2] + b0, v11 = acc[mt][nt][3] + b1v;
            size_t o0 = (size_t)row * NOUT + col;
            size_t o1 = (size_t)(row + 8) * NOUT + col;
            *(float2*)&Cf[o0] = make_float2(v00, v01);
            *(float2*)&Cf[o1] = make_float2(v10, v11);
            *(__half2*)&Ch[o0] = __floats2half2_rn(v00, v01);
            *(__half2*)&Ch[o1] = __floats2half2_rn(v10, v11);
        }
    }
}

// ================= PQ GEMM: single-term fp16, BK=64 ==========================
__device__ __forceinline__ void ld_chunk2(uint32_t sbase,
                                          const __half* A, const __half* B,
                                          int bm0, int bn0, int k0, int tid) {
#pragma unroll
    for (int p = tid; p < 2048; p += 256) {
        int q = p & 1023;
        int row = q >> 3, seg = q & 7;
        uint32_t soff = (uint32_t)(row * ROWB2 + seg * 16);
        if (p < 1024) {
            size_t ga = ((size_t)(bm0 + row) * HC + k0 + seg * 8) * 2;
            cp16(sbase + soff, (const char*)A + ga);
        } else {
            size_t gb = ((size_t)(bn0 + row) * HC + k0 + seg * 8) * 2;
            cp16(sbase + PLANE2 + soff, (const char*)B + gb);
        }
    }
}

__global__ __launch_bounds__(256, 2)
void gemm_pq_k(const __half* __restrict__ A, const __half* __restrict__ B,
               __half* __restrict__ C) {
    extern __shared__ char smem[];
    const uint32_t sb = smem_u32(smem);
    const int tid = threadIdx.x;
    const int wid = tid >> 5, lane = tid & 31;
    const int warp_m = wid & 3;
    const int warp_n = wid >> 2;
    const int bm0 = blockIdx.y * BM;
    const int bn0 = blockIdx.x * BN;

    float acc[2][8][4];
#pragma unroll
    for (int i = 0; i < 2; i++)
#pragma unroll
        for (int j = 0; j < 8; j++)
#pragma unroll
            for (int k = 0; k < 4; k++) acc[i][j][k] = 0.f;

    const int nch = HC / 64;   // 8

    ld_chunk2(sb, A, B, bm0, bn0, 0, tid);
    asm volatile("cp.async.commit_group;" ::: "memory");

    const uint32_t a_row = (uint32_t)(warp_m * 32 + (lane & 15));
    const uint32_t a_k8  = (uint32_t)((lane >> 4) * 8);
    const uint32_t b_row = (uint32_t)(warp_n * 64 + (lane & 7) + ((lane >> 4) << 3));
    const uint32_t b_k8  = (uint32_t)(((lane >> 3) & 1) * 8);

    int stage = 0;
    for (int c = 0; c < nch; ++c) {
        if (c + 1 < nch) {
            ld_chunk2(sb + (stage ^ 1) * STG2, A, B, bm0, bn0, (c + 1) * 64, tid);
            asm volatile("cp.async.commit_group;" ::: "memory");
            asm volatile("cp.async.wait_group 1;" ::: "memory");
        } else {
            asm volatile("cp.async.wait_group 0;" ::: "memory");
        }
        __syncthreads();

        const uint32_t s = sb + stage * STG2;
        const uint32_t sA = s, sB = s + PLANE2;

#pragma unroll
        for (int ks = 0; ks < 4; ks++) {
            const uint32_t aoff = a_row * ROWB2 + (ks * 16 + a_k8) * 2;
            const uint32_t boff = b_row * ROWB2 + (ks * 16 + b_k8) * 2;

            uint32_t a1[2][4], b1[8][2];
            ldm4(a1[0], sA + aoff);
            ldm4(a1[1], sA + aoff + 16 * ROWB2);
#pragma unroll
            for (int bt = 0; bt < 4; bt++) {
                uint32_t r[4];
                ldm4(r, sB + boff + bt * 16 * ROWB2);
                b1[2 * bt][0] = r[0]; b1[2 * bt][1] = r[1];
                b1[2 * bt + 1][0] = r[2]; b1[2 * bt + 1][1] = r[3];
            }
#pragma unroll
            for (int mt = 0; mt < 2; mt++)
#pragma unroll
                for (int nt = 0; nt < 8; nt++)
                    mma16816(acc[mt][nt], a1[mt], b1[nt]);
        }
        __syncthreads();
        stage ^= 1;
    }

    const int r0 = bm0 + warp_m * 32 + (lane >> 2);
    const int c0 = bn0 + warp_n * 64 + (lane & 3) * 2;
#pragma unroll
    for (int mt = 0; mt < 2; mt++) {
#pragma unroll
        for (int nt = 0; nt < 8; nt++) {
            int col = c0 + nt * 8;
            int row = r0 + mt * 16;
            size_t o0 = (size_t)row * NOUT2 + col;
            size_t o1 = (size_t)(row + 8) * NOUT2 + col;
            *(__half2*)&C[o0] = __floats2half2_rn(acc[mt][nt][0], acc[mt][nt][1]);
            *(__half2*)&C[o1] = __floats2half2_rn(acc[mt][nt][2], acc[mt][nt][3]);
        }
    }
}

// ---------------- split / pack kernels --------------------------------------
__global__ void split_x_k(const float* __restrict__ x) {
    int i = blockIdx.x * 256 + threadIdx.x;   // NN*128
    int n = i >> 7, c = i & 127;
    float v = (c < 118) ? x[n * 118 + c] : 0.f;
    __half a, b; split16(v, a, b);
    g_x1[i] = a; g_x2[i] = b;
}

__global__ void pack_wa_k(const float* __restrict__ Wa) {
    int i = blockIdx.x * 256 + threadIdx.x;   // 1024*512
    int n = i >> 9, k = i & 511;
    float v = (n < HC) ? Wa[(size_t)k * HC + n]
                       : Wa[(size_t)(HC + k) * HC + (n - HC)];
    g_Wc1[n * HC + k] = __float2half_rn(v);
}

__global__ void pack_wn_k(const float* __restrict__ Wn) {
    int i = blockIdx.x * 256 + threadIdx.x;   // 512*128
    int n = i >> 7, k = i & 127;
    float v = (k < 118) ? Wn[(size_t)k * HC + n] : 0.f;
    __half a, b; split16(v, a, b);
    int o = n * KPAD + k;
    g_WnT1[o] = a; g_WnT2[o] = b;
}

// ---------------- CSR build --------------------------------------------------
__global__ void zero_k() {
    int i = blockIdx.x * 256 + threadIdx.x;
    if (i < NN) { g_deg[i] = 0; g_cursor[i] = 0; }
}
__global__ void count_k(const int* __restrict__ dst) {
    int e = blockIdx.x * 256 + threadIdx.x;
    if (e < NE) atomicAdd(&g_deg[dst[e]], 1);
}
__global__ void scan_k() {
    __shared__ int sums[1024];
    int tid = threadIdx.x;
    int base = tid * 32;
    int local[32];
    int run = 0;
#pragma unroll
    for (int i = 0; i < 32; i++) { local[i] = run; run += g_deg[base + i]; }
    sums[tid] = run;
    __syncthreads();
    for (int off = 1; off < 1024; off <<= 1) {
        int v = (tid >= off) ? sums[tid - off] : 0;
        __syncthreads();
        sums[tid] += v;
        __syncthreads();
    }
    int offset = (tid == 0) ? 0 : sums[tid - 1];
#pragma unroll
    for (int i = 0; i < 32; i++) g_start[base + i] = offset + local[i];
    if (tid == 1023) g_start[NN] = sums[1023];
}
__global__ void scatter_k(const int* __restrict__ dst) {
    int e = blockIdx.x * 256 + threadIdx.x;
    if (e < NE) {
        int d = dst[e];
        int p = atomicAdd(&g_cursor[d], 1);
        g_eidx[g_start[d] + p] = e;
    }
}

// ---------------- fused scores + edge softmax (one warp per dst node) -------
// Lane layout: g = lane>>3 owns head p*4+g in pass p; l8 = lane&7 covers
// channels h*32 + j*8 + l8 (half2 index). One 3-level butterfly reduces 4
// heads at once; 4 broadcasts recover them on all lanes: 14 shfl/edge vs 40.
__global__ void fused_attn_k(const __half2* __restrict__ PQ,
                             const float* __restrict__ ba, const float* __restrict__ aw,
                             const int* __restrict__ src) {
    int node = (blockIdx.x * blockDim.x + threadIdx.x) >> 5;
    int lane = threadIdx.x & 31;
    if (node >= NN) return;
    int g = lane >> 3, l8 = lane & 7;

    const float2* baf = (const float2*)ba;
    const float2* awf = (const float2*)aw;
    const __half2* Qr = PQ + (size_t)node * 512 + 256;

    // per-lane channel slots: qb = Q + ba (folded), aw2 = attention weights
    float2 qb[2][4], aw2[2][4];
    int pidx[2][4];
#pragma unroll
    for (int p = 0; p < 2; p++)
#pragma unroll
        for (int j = 0; j < 4; j++) {
            int idx = (p * 4 + g) * 32 + j * 8 + l8;
            pidx[p][j] = idx;
            float2 q = __half22float2(Qr[idx]);
            float2 b = baf[idx];
            qb[p][j] = make_float2(q.x + b.x, q.y + b.y);
            aw2[p][j] = awf[idx];
        }

    int s0 = g_start[node];
    int deg = g_start[node + 1] - s0;

    int eA = 0, sA = 0, eB = 0, sB = 0;
    if (lane < deg)      { eA = g_eidx[s0 + lane];      sA = src[eA]; }
    if (lane + 32 < deg) { eB = g_eidx[s0 + lane + 32]; sB = src[eB]; }

    float m[8], myS0[8], myS1[8];
#pragma unroll
    for (int h = 0; h < 8; h++) m[h] = -1e30f;

    int dmain = deg < 64 ? deg : 64;
    for (int j = 0; j < dmain; j++) {
        int s = (j < 32) ? __shfl_sync(0xffffffffu, sA, j)
                         : __shfl_sync(0xffffffffu, sB, j - 32);
        const __half2* Pr = PQ + (size_t)s * 512;
        float sc[8];
#pragma unroll
        for (int p = 0; p < 2; p++) {
            float v = 0.f;
#pragma unroll
            for (int jj = 0; jj < 4; jj++) {
                float2 pv = __half22float2(Pr[pidx[p][jj]]);
                float z0 = pv.x + qb[p][jj].x; z0 = z0 > 0.f ? z0 : 0.01f * z0;
                float z1 = pv.y + qb[p][jj].y; z1 = z1 > 0.f ? z1 : 0.01f * z1;
                v = fmaf(z0, aw2[p][jj].x, fmaf(z1, aw2[p][jj].y, v));
            }
            v += __shfl_xor_sync(0xffffffffu, v, 4);
            v += __shfl_xor_sync(0xffffffffu, v, 2);
            v += __shfl_xor_sync(0xffffffffu, v, 1);
#pragma unroll
            for (int k = 0; k < 4; k++)
                sc[p * 4 + k] = __shfl_sync(0xffffffffu, v, k * 8);
        }
#pragma unroll
        for (int h = 0; h < 8; h++) m[h] = fmaxf(m[h], sc[h]);
        if (j < 32) {
            if (lane == j) {
#pragma unroll
                for (int h = 0; h < 8; h++) myS0[h] = sc[h];
            }
        } else if (lane == j - 32) {
#pragma unroll
            for (int h = 0; h < 8; h++) myS1[h] = sc[h];
        }
    }
    // rare tail deg > 64: same scoring, lane-0 spill to g_score
    for (int j = 64; j < deg; j++) {
        int e = g_eidx[s0 + j];
        int s = src[e];
        const __half2* Pr = PQ + (size_t)s * 512;
        float sc[8];
#pragma unroll
        for (int p = 0; p < 2; p++) {
            float v = 0.f;
#pragma unroll
            for (int jj = 0; jj < 4; jj++) {
                float2 pv = __half22float2(Pr[pidx[p][jj]]);
                float z0 = pv.x + qb[p][jj].x; z0 = z0 > 0.f ? z0 : 0.01f * z0;
                float z1 = pv.y + qb[p][jj].y; z1 = z1 > 0.f ? z1 : 0.01f * z1;
                v = fmaf(z0, aw2[p][jj].x, fmaf(z1, aw2[p][jj].y, v));
            }
            v += __shfl_xor_sync(0xffffffffu, v, 4);
            v += __shfl_xor_sync(0xffffffffu, v, 2);
            v += __shfl_xor_sync(0xffffffffu, v, 1);
#pragma unroll
            for (int k = 0; k < 4; k++)
                sc[p * 4 + k] = __shfl_sync(0xffffffffu, v, k * 8);
        }
#pragma unroll
        for (int h = 0; h < 8; h++) m[h] = fmaxf(m[h], sc[h]);
        if (lane == 0) {
#pragma unroll
            for (int h = 0; h < 8; h++) g_score[e * 8 + h] = sc[h];
        }
    }

    float ex0[8], ex1[8], dsum[8];
#pragma unroll
    for (int h = 0; h < 8; h++) dsum[h] = 0.f;
    if (lane < deg) {
#pragma unroll
        for (int h = 0; h < 8; h++) { ex0[h] = __expf(myS0[h] - m[h]); dsum[h] += ex0[h]; }
    }
    if (lane + 32 < deg) {
#pragma unroll
        for (int h = 0; h < 8; h++) { ex1[h] = __expf(myS1[h] - m[h]); dsum[h] += ex1[h]; }
    }
    if (lane == 0) {
        for (int j = 64; j < deg; j++) {
            int e = g_eidx[s0 + j];
#pragma unroll
            for (int h = 0; h < 8; h++) dsum[h] += __expf(g_score[e * 8 + h] - m[h]);
        }
    }
#pragma unroll
    for (int h = 0; h < 8; h++)
#pragma unroll
        for (int o = 16; o; o >>= 1)
            dsum[h] += __shfl_xor_sync(0xffffffffu, dsum[h], o);

    float inv[8];
#pragma unroll
    for (int h = 0; h < 8; h++) inv[h] = 1.f / dsum[h];

    if (lane < deg) {
        *(float4*)&g_score[eA * 8] =
            make_float4(ex0[0] * inv[0], ex0[1] * inv[1], ex0[2] * inv[2], ex0[3] * inv[3]);
        *(float4*)&g_score[eA * 8 + 4] =
            make_float4(ex0[4] * inv[4], ex0[5] * inv[5], ex0[6] * inv[6], ex0[7] * inv[7]);
    }
    if (lane + 32 < deg) {
        *(float4*)&g_score[eB * 8] =
            make_float4(ex1[0] * inv[0], ex1[1] * inv[1], ex1[2] * inv[2], ex1[3] * inv[3]);
        *(float4*)&g_score[eB * 8 + 4] =
            make_float4(ex1[4] * inv[4], ex1[5] * inv[5], ex1[6] * inv[6], ex1[7] * inv[7]);
    }
    if (lane == 0) {
        for (int j = 64; j < deg; j++) {
            int e = g_eidx[s0 + j];
#pragma unroll
            for (int h = 0; h < 8; h++)
                g_score[e * 8 + h] = __expf(g_score[e * 8 + h] - m[h]) * inv[h];
        }
    }
}

// ---------------- weighted aggregation (+ optional fp16 plane) ---------------
__global__ void agg_k(const float* __restrict__ hin, const int* __restrict__ src,
                      float* __restrict__ hout, __half* __restrict__ o1) {
    int node = blockIdx.x;
    int t = threadIdx.x;
    int lane = t & 31;
    int hd = t >> 4;
    int s0 = g_start[node], s1 = g_start[node + 1];
    int deg = s1 - s0;

    int eA = 0, snA = 0, eB = 0, snB = 0;
    if (lane < deg)      { eA = g_eidx[s0 + lane];      snA = src[eA]; }
    if (lane + 32 < deg) { eB = g_eidx[s0 + lane + 32]; snB = src[eB]; }

    float4 acc = make_float4(0.f, 0.f, 0.f, 0.f);
    int dmain = deg < 64 ? deg : 64;
    for (int i = 0; i < dmain; i++) {
        int e, sn;
        if (i < 32) {
            e  = __shfl_sync(0xffffffffu, eA, i);
            sn = __shfl_sync(0xffffffffu, snA, i);
        } else {
            e  = __shfl_sync(0xffffffffu, eB, i - 32);
            sn = __shfl_sync(0xffffffffu, snB, i - 32);
        }
        float a = g_score[e * 8 + hd];
        float4 v = ((const float4*)hin)[(size_t)sn * 128 + t];
        acc.x = fmaf(a, v.x, acc.x);
        acc.y = fmaf(a, v.y, acc.y);
        acc.z = fmaf(a, v.z, acc.z);
        acc.w = fmaf(a, v.w, acc.w);
    }
    for (int i = 64; i < deg; i++) {
        int e = g_eidx[s0 + i];
        int sn = src[e];
        float a = g_score[e * 8 + hd];
        float4 v = ((const float4*)hin)[(size_t)sn * 128 + t];
        acc.x = fmaf(a, v.x, acc.x);
        acc.y = fmaf(a, v.y, acc.y);
        acc.z = fmaf(a, v.z, acc.z);
        acc.w = fmaf(a, v.w, acc.w);
    }
    ((float4*)hout)[(size_t)node * 128 + t] = acc;
    if (o1) {
        size_t o = (size_t)node * 512 + t * 4;
        *(__half2*)&o1[o]     = __floats2half2_rn(acc.x, acc.y);
        *(__half2*)&o1[o + 2] = __floats2half2_rn(acc.z, acc.w);
    }
}

// ---------------- launch ----------------------------------------------------
extern "C" void kernel_launch(void* const* d_in, const int* in_sizes, int n_in,
                              void* d_out, int out_size) {
    (void)in_sizes; (void)n_in; (void)out_size;
    const float* x   = (const float*)d_in[0];
    const int*   src = (const int*)d_in[2];
    const int*   dst = (const int*)d_in[3];
    const float* Wn  = (const float*)d_in[4];
    const float* bn  = (const float*)d_in[5];
    const float* Wa  = (const float*)d_in[8];
    const float* ba  = (const float*)d_in[9];
    const float* aw  = (const float*)d_in[10];
    float* out = (float*)d_out;

    const int SMEM4 = 2 * 4 * PLANE_B;   // 81920  (h0: 3-term, BK=32)
    cudaFuncSetAttribute(gemm_h0_k, cudaFuncAttributeMaxDynamicSharedMemorySize, SMEM4);
    cudaFuncSetAttribute(gemm_pq_k, cudaFuncAttributeMaxDynamicSharedMemorySize, SMEM2);

    float *p_h, *p_h2;
    __half *p_PQh, *p_x1, *p_x2, *p_hA1, *p_WnT1, *p_WnT2, *p_Wc1;
    cudaGetSymbolAddress((void**)&p_h,    g_h);
    cudaGetSymbolAddress((void**)&p_h2,   g_h2);
    cudaGetSymbolAddress((void**)&p_PQh,  g_PQh);
    cudaGetSymbolAddress((void**)&p_x1,   g_x1);
    cudaGetSymbolAddress((void**)&p_x2,   g_x2);
    cudaGetSymbolAddress((void**)&p_hA1,  g_hA1);
    cudaGetSymbolAddress((void**)&p_WnT1, g_WnT1);
    cudaGetSymbolAddress((void**)&p_WnT2, g_WnT2);
    cudaGetSymbolAddress((void**)&p_Wc1,  g_Wc1);

    dim3 g_h0(HC / BN, NN / BM);       // (4, 256)
    dim3 g_pq(NOUT2 / BN, NN / BM);    // (8, 256)

    // prep, then h0 GEMM early so the profiler window lands on a GEMM
    split_x_k<<<NN * KPAD / 256, 256>>>(x);
    pack_wn_k<<<HC * KPAD / 256, 256>>>(Wn);
    pack_wa_k<<<NOUT2 * HC / 256, 256>>>(Wa);

    // h0 = x @ Wn + bn : fp32 h + fp16 h plane (3-term compensated)
    gemm_h0_k<<<g_h0, 256, SMEM4>>>(p_x1, p_x2, p_WnT1, p_WnT2, bn,
                                    p_h, p_hA1, KPAD, HC);

    // CSR build
    zero_k<<<NN / 256, 256>>>();
    count_k<<<NE / 256, 256>>>(dst);
    scan_k<<<1, 1024>>>();
    scatter_k<<<NE / 256, 256>>>(dst);

    // ---- layer 1 ----
    gemm_pq_k<<<g_pq, 256, SMEM2>>>(p_hA1, p_Wc1, p_PQh);
    fused_attn_k<<<NN / 8, 256>>>((const __half2*)p_PQh, ba, aw, src);
    agg_k<<<NN, 128>>>(p_h, src, p_h2, p_hA1);

    // ---- layer 2 ----
    gemm_pq_k<<<g_pq, 256, SMEM2>>>(p_hA1, p_Wc1, p_PQh);
    fused_attn_k<<<NN / 8, 256>>>((const __half2*)p_PQh, ba, aw, src);
    agg_k<<<NN, 128>>>(p_h2, src, out, nullptr);
}

// round 16
// speedup vs baseline: 1.4652x; 1.4652x over previous
#include <cuda_runtime.h>
#include <cuda_fp16.h>
#include <cstdint>

#define NN 32768
#define NE 262144
#define HC 512
#define KPAD 128
#define NOUT2 1024

// h0 GEMM tiling (BK=32, compensated 3-term)
#define BM 128
#define BN 128
#define BK 32
#define ROWB 80                       // 32 halfs + 16B pad
#define PLANE_B (128 * ROWB)          // 10240

// PQ GEMM tiling (BK=64, single-term fp16)
#define ROWB2 144                     // 64 halfs + 16B pad
#define PLANE2 (128 * ROWB2)          // 18432
#define STG2 (2 * PLANE2)             // 36864 (A,B)
#define SMEM2 (2 * STG2)              // 73728

// ---------------- scratch (static device globals) ---------------------------
__device__ float g_h[NN * HC];
__device__ float g_h2[NN * HC];
__device__ __half g_PQh[NN * NOUT2];  // [P | Q] per row, fp16 (64MB, L2-resident)
__device__ float g_score[NE * 8];     // alpha (+ rare overflow scratch)
__device__ int   g_deg[NN];
__device__ int   g_cursor[NN];
__device__ int   g_start[NN + 1];
__device__ int   g_eidx[NE];

__device__ __half g_x1[NN * KPAD];    // x hi/lo planes (h0 is fully compensated)
__device__ __half g_x2[NN * KPAD];
__device__ __half g_hA1[NN * HC];     // fp16 h plane (PQ GEMM input)
__device__ __half g_WnT1[HC * KPAD];
__device__ __half g_WnT2[HC * KPAD];
__device__ __half g_Wc1[NOUT2 * HC];  // combined Wa^T hi plane

// ---------------- ptx helpers -----------------------------------------------
__device__ __forceinline__ uint32_t smem_u32(const void* p) {
    uint32_t a;
    asm("{ .reg .u64 t; cvta.to.shared.u64 t, %1; cvt.u32.u64 %0, t; }" : "=r"(a) : "l"(p));
    return a;
}
__device__ __forceinline__ void cp16(uint32_t dst, const void* src) {
    asm volatile("cp.async.cg.shared.global [%0], [%1], 16;" :: "r"(dst), "l"(src) : "memory");
}
__device__ __forceinline__ void ldm4(uint32_t* r, uint32_t addr) {
    asm volatile("ldmatrix.sync.aligned.m8n8.x4.shared.b16 {%0,%1,%2,%3}, [%4];"
                 : "=r"(r[0]), "=r"(r[1]), "=r"(r[2]), "=r"(r[3]) : "r"(addr));
}
__device__ __forceinline__ void mma16816(float* c, const uint32_t* a, const uint32_t* b) {
    asm volatile(
        "mma.sync.aligned.m16n8k16.row.col.f32.f16.f16.f32 "
        "{%0,%1,%2,%3}, {%4,%5,%6,%7}, {%8,%9}, {%0,%1,%2,%3};"
        : "+f"(c[0]), "+f"(c[1]), "+f"(c[2]), "+f"(c[3])
        : "r"(a[0]), "r"(a[1]), "r"(a[2]), "r"(a[3]), "r"(b[0]), "r"(b[1]));
}
__device__ __forceinline__ void split16(float v, __half& hi, __half& lo) {
    hi = __float2half_rn(v);
    lo = __float2half_rn(v - __half2float(hi));
}

// ================= h0 GEMM: compensated 3-term, BK=32 ========================
__device__ __forceinline__ void ld_chunk4(uint32_t sbase,
                                          const __half* A1, const __half* A2,
                                          const __half* B1, const __half* B2,
                                          int bm0, int bn0, int K, int k0, int tid) {
#pragma unroll
    for (int p = tid; p < 512; p += 256) {
        int row = p >> 2, seg = p & 3;
        uint32_t soff = (uint32_t)(row * ROWB + seg * 16);
        size_t ga = ((size_t)(bm0 + row) * K + k0 + seg * 8) * 2;
        size_t gb = ((size_t)(bn0 + row) * K + k0 + seg * 8) * 2;
        cp16(sbase + soff,               (const char*)A1 + ga);
        cp16(sbase + PLANE_B + soff,     (const char*)A2 + ga);
        cp16(sbase + 2 * PLANE_B + soff, (const char*)B1 + gb);
        cp16(sbase + 3 * PLANE_B + soff, (const char*)B2 + gb);
    }
}

__global__ __launch_bounds__(256, 2)
void gemm_h0_k(const __half* __restrict__ A1, const __half* __restrict__ A2,
               const __half* __restrict__ B1, const __half* __restrict__ B2,
               const float* __restrict__ bias, float* __restrict__ Cf,
               __half* __restrict__ Ch, int K, int NOUT) {
    constexpr uint32_t STG_T = 4 * PLANE_B;
    extern __shared__ char smem[];
    const uint32_t sb = smem_u32(smem);
    const int tid = threadIdx.x;
    const int wid = tid >> 5, lane = tid & 31;
    const int warp_m = wid & 3;
    const int warp_n = wid >> 2;
    const int bm0 = blockIdx.y * BM;
    const int bn0 = blockIdx.x * BN;

    float acc[2][8][4];
#pragma unroll
    for (int i = 0; i < 2; i++)
#pragma unroll
        for (int j = 0; j < 8; j++)
#pragma unroll
            for (int k = 0; k < 4; k++) acc[i][j][k] = 0.f;

    const int nch = K / BK;

    ld_chunk4(sb, A1, A2, B1, B2, bm0, bn0, K, 0, tid);
    asm volatile("cp.async.commit_group;" ::: "memory");

    const uint32_t a_row = (uint32_t)(warp_m * 32 + (lane & 15));
    const uint32_t a_k8  = (uint32_t)((lane >> 4) * 8);
    const uint32_t b_row = (uint32_t)(warp_n * 64 + (lane & 7) + ((lane >> 4) << 3));
    const uint32_t b_k8  = (uint32_t)(((lane >> 3) & 1) * 8);

    int stage = 0;
    for (int c = 0; c < nch; ++c) {
        if (c + 1 < nch) {
            ld_chunk4(sb + (stage ^ 1) * STG_T, A1, A2, B1, B2, bm0, bn0, K,
                      (c + 1) * BK, tid);
            asm volatile("cp.async.commit_group;" ::: "memory");
            asm volatile("cp.async.wait_group 1;" ::: "memory");
        } else {
            asm volatile("cp.async.wait_group 0;" ::: "memory");
        }
        __syncthreads();

        const uint32_t s = sb + stage * STG_T;
        const uint32_t sA1 = s, sA2 = s + PLANE_B;
        const uint32_t sB1 = s + 2 * PLANE_B, sB2 = s + 3 * PLANE_B;

#pragma unroll
        for (int ks = 0; ks < 2; ks++) {
            const uint32_t aoff = a_row * ROWB + (ks * 16 + a_k8) * 2;
            const uint32_t boff = b_row * ROWB + (ks * 16 + b_k8) * 2;

            uint32_t a1[2][4], b1[8][2];
            ldm4(a1[0], sA1 + aoff);
            ldm4(a1[1], sA1 + aoff + 16 * ROWB);
#pragma unroll
            for (int bt = 0; bt < 4; bt++) {
                uint32_t r[4];
                ldm4(r, sB1 + boff + bt * 16 * ROWB);
                b1[2 * bt][0] = r[0]; b1[2 * bt][1] = r[1];
                b1[2 * bt + 1][0] = r[2]; b1[2 * bt + 1][1] = r[3];
            }
#pragma unroll
            for (int mt = 0; mt < 2; mt++)
#pragma unroll
                for (int nt = 0; nt < 8; nt++)
                    mma16816(acc[mt][nt], a1[mt], b1[nt]);

            {   // A2 x B1
                uint32_t a2[2][4];
                ldm4(a2[0], sA2 + aoff);
                ldm4(a2[1], sA2 + aoff + 16 * ROWB);
#pragma unroll
                for (int mt = 0; mt < 2; mt++)
#pragma unroll
                    for (int nt = 0; nt < 8; nt++)
                        mma16816(acc[mt][nt], a2[mt], b1[nt]);
            }
            {   // A1 x B2
                uint32_t b2[8][2];
#pragma unroll
                for (int bt = 0; bt < 4; bt++) {
                    uint32_t r[4];
                    ldm4(r, sB2 + boff + bt * 16 * ROWB);
                    b2[2 * bt][0] = r[0]; b2[2 * bt][1] = r[1];
                    b2[2 * bt + 1][0] = r[2]; b2[2 * bt + 1][1] = r[3];
                }
#pragma unroll
                for (int mt = 0; mt < 2; mt++)
#pragma unroll
                    for (int nt = 0; nt < 8; nt++)
                        mma16816(acc[mt][nt], a1[mt], b2[nt]);
            }
        }
        __syncthreads();
        stage ^= 1;
    }

    const int r0 = bm0 + warp_m * 32 + (lane >> 2);
    const int c0 = bn0 + warp_n * 64 + (lane & 3) * 2;
#pragma unroll
    for (int mt = 0; mt < 2; mt++) {
#pragma unroll
        for (int nt = 0; nt < 8; nt++) {
            int col = c0 + nt * 8;
            float b0 = bias[col], b1v = bias[col + 1];
            int row = r0 + mt * 16;
            float v00 = acc[mt][nt][0] + b0, v01 = acc[mt][nt][1] + b1v;
            float v10 = acc[mt][nt][2] + b0, v11 = acc[mt][nt][3] + b1v;
            size_t o0 = (size_t)row * NOUT + col;
            size_t o1 = (size_t)(row + 8) * NOUT + col;
            *(float2*)&Cf[o0] = make_float2(v00, v01);
            *(float2*)&Cf[o1] = make_float2(v10, v11);
            *(__half2*)&Ch[o0] = __floats2half2_rn(v00, v01);
            *(__half2*)&Ch[o1] = __floats2half2_rn(v10, v11);
        }
    }
}

// ================= PQ GEMM: single-term fp16, BK=64 ==========================
__device__ __forceinline__ void ld_chunk2(uint32_t sbase,
                                          const __half* A, const __half* B,
                                          int bm0, int bn0, int k0, int tid) {
#pragma unroll
    for (int p = tid; p < 2048; p += 256) {
        int q = p & 1023;
        int row = q >> 3, seg = q & 7;
        uint32_t soff = (uint32_t)(row * ROWB2 + seg * 16);
        if (p < 1024) {
            size_t ga = ((size_t)(bm0 + row) * HC + k0 + seg * 8) * 2;
            cp16(sbase + soff, (const char*)A + ga);
        } else {
            size_t gb = ((size_t)(bn0 + row) * HC + k0 + seg * 8) * 2;
            cp16(sbase + PLANE2 + soff, (const char*)B + gb);
        }
    }
}

__global__ __launch_bounds__(256, 2)
void gemm_pq_k(const __half* __restrict__ A, const __half* __restrict__ B,
               __half* __restrict__ C) {
    extern __shared__ char smem[];
    const uint32_t sb = smem_u32(smem);
    const int tid = threadIdx.x;
    const int wid = tid >> 5, lane = tid & 31;
    const int warp_m = wid & 3;
    const int warp_n = wid >> 2;
    const int bm0 = blockIdx.y * BM;
    const int bn0 = blockIdx.x * BN;

    float acc[2][8][4];
#pragma unroll
    for (int i = 0; i < 2; i++)
#pragma unroll
        for (int j = 0; j < 8; j++)
#pragma unroll
            for (int k = 0; k < 4; k++) acc[i][j][k] = 0.f;

    const int nch = HC / 64;   // 8

    ld_chunk2(sb, A, B, bm0, bn0, 0, tid);
    asm volatile("cp.async.commit_group;" ::: "memory");

    const uint32_t a_row = (uint32_t)(warp_m * 32 + (lane & 15));
    const uint32_t a_k8  = (uint32_t)((lane >> 4) * 8);
    const uint32_t b_row = (uint32_t)(warp_n * 64 + (lane & 7) + ((lane >> 4) << 3));
    const uint32_t b_k8  = (uint32_t)(((lane >> 3) & 1) * 8);

    int stage = 0;
    for (int c = 0; c < nch; ++c) {
        if (c + 1 < nch) {
            ld_chunk2(sb + (stage ^ 1) * STG2, A, B, bm0, bn0, (c + 1) * 64, tid);
            asm volatile("cp.async.commit_group;" ::: "memory");
            asm volatile("cp.async.wait_group 1;" ::: "memory");
        } else {
            asm volatile("cp.async.wait_group 0;" ::: "memory");
        }
        __syncthreads();

        const uint32_t s = sb + stage * STG2;
        const uint32_t sA = s, sB = s + PLANE2;

#pragma unroll
        for (int ks = 0; ks < 4; ks++) {
            const uint32_t aoff = a_row * ROWB2 + (ks * 16 + a_k8) * 2;
            const uint32_t boff = b_row * ROWB2 + (ks * 16 + b_k8) * 2;

            uint32_t a1[2][4], b1[8][2];
            ldm4(a1[0], sA + aoff);
            ldm4(a1[1], sA + aoff + 16 * ROWB2);
#pragma unroll
            for (int bt = 0; bt < 4; bt++) {
                uint32_t r[4];
                ldm4(r, sB + boff + bt * 16 * ROWB2);
                b1[2 * bt][0] = r[0]; b1[2 * bt][1] = r[1];
                b1[2 * bt + 1][0] = r[2]; b1[2 * bt + 1][1] = r[3];
            }
#pragma unroll
            for (int mt = 0; mt < 2; mt++)
#pragma unroll
                for (int nt = 0; nt < 8; nt++)
                    mma16816(acc[mt][nt], a1[mt], b1[nt]);
        }
        __syncthreads();
        stage ^= 1;
    }

    const int r0 = bm0 + warp_m * 32 + (lane >> 2);
    const int c0 = bn0 + warp_n * 64 + (lane & 3) * 2;
#pragma unroll
    for (int mt = 0; mt < 2; mt++) {
#pragma unroll
        for (int nt = 0; nt < 8; nt++) {
            int col = c0 + nt * 8;
            int row = r0 + mt * 16;
            size_t o0 = (size_t)row * NOUT2 + col;
            size_t o1 = (size_t)(row + 8) * NOUT2 + col;
            *(__half2*)&C[o0] = __floats2half2_rn(acc[mt][nt][0], acc[mt][nt][1]);
            *(__half2*)&C[o1] = __floats2half2_rn(acc[mt][nt][2], acc[mt][nt][3]);
        }
    }
}

// ---------------- split / pack kernels --------------------------------------
__global__ void split_x_k(const float* __restrict__ x) {
    int i = blockIdx.x * 256 + threadIdx.x;   // NN*128
    int n = i >> 7, c = i & 127;
    float v = (c < 118) ? x[n * 118 + c] : 0.f;
    __half a, b; split16(v, a, b);
    g_x1[i] = a; g_x2[i] = b;
}

__global__ void pack_wa_k(const float* __restrict__ Wa) {
    int i = blockIdx.x * 256 + threadIdx.x;   // 1024*512
    int n = i >> 9, k = i & 511;
    float v = (n < HC) ? Wa[(size_t)k * HC + n]
                       : Wa[(size_t)(HC + k) * HC + (n - HC)];
    g_Wc1[n * HC + k] = __float2half_rn(v);
}

__global__ void pack_wn_k(const float* __restrict__ Wn) {
    int i = blockIdx.x * 256 + threadIdx.x;   // 512*128
    int n = i >> 7, k = i & 127;
    float v = (k < 118) ? Wn[(size_t)k * HC + n] : 0.f;
    __half a, b; split16(v, a, b);
    int o = n * KPAD + k;
    g_WnT1[o] = a; g_WnT2[o] = b;
}

// ---------------- CSR build --------------------------------------------------
__global__ void zero_k() {
    int i = blockIdx.x * 256 + threadIdx.x;
    if (i < NN) { g_deg[i] = 0; g_cursor[i] = 0; }
}
__global__ void count_k(const int* __restrict__ dst) {
    int e = blockIdx.x * 256 + threadIdx.x;
    if (e < NE) atomicAdd(&g_deg[dst[e]], 1);
}
__global__ void scan_k() {
    __shared__ int sums[1024];
    int tid = threadIdx.x;
    int base = tid * 32;
    int local[32];
    int run = 0;
#pragma unroll
    for (int i = 0; i < 32; i++) { local[i] = run; run += g_deg[base + i]; }
    sums[tid] = run;
    __syncthreads();
    for (int off = 1; off < 1024; off <<= 1) {
        int v = (tid >= off) ? sums[tid - off] : 0;
        __syncthreads();
        sums[tid] += v;
        __syncthreads();
    }
    int offset = (tid == 0) ? 0 : sums[tid - 1];
#pragma unroll
    for (int i = 0; i < 32; i++) g_start[base + i] = offset + local[i];
    if (tid == 1023) g_start[NN] = sums[1023];
}
__global__ void scatter_k(const int* __restrict__ dst) {
    int e = blockIdx.x * 256 + threadIdx.x;
    if (e < NE) {
        int d = dst[e];
        int p = atomicAdd(&g_cursor[d], 1);
        g_eidx[g_start[d] + p] = e;
    }
}

// ---------------- fused scores + edge softmax (one warp per dst node) -------
// Lane layout: g = lane>>3 owns head p*4+g in pass p; l8 = lane&7 covers
// channels h*32 + j*8 + l8 (half2 index). One 3-level butterfly reduces 4
// heads at once; 4 broadcasts recover them on all lanes: 14 shfl/edge vs 40.
__global__ void fused_attn_k(const __half2* __restrict__ PQ,
                             const float* __restrict__ ba, const float* __restrict__ aw,
                             const int* __restrict__ src) {
    int node = (blockIdx.x * blockDim.x + threadIdx.x) >> 5;
    int lane = threadIdx.x & 31;
    if (node >= NN) return;
    int g = lane >> 3, l8 = lane & 7;

    const float2* baf = (const float2*)ba;
    const float2* awf = (const float2*)aw;
    const __half2* Qr = PQ + (size_t)node * 512 + 256;

    // per-lane channel slots: qb = Q + ba (folded), aw2 = attention weights
    float2 qb[2][4], aw2[2][4];
    int pidx[2][4];
#pragma unroll
    for (int p = 0; p < 2; p++)
#pragma unroll
        for (int j = 0; j < 4; j++) {
            int idx = (p * 4 + g) * 32 + j * 8 + l8;
            pidx[p][j] = idx;
            float2 q = __half22float2(Qr[idx]);
            float2 b = baf[idx];
            qb[p][j] = make_float2(q.x + b.x, q.y + b.y);
            aw2[p][j] = awf[idx];
        }

    int s0 = g_start[node];
    int deg = g_start[node + 1] - s0;

    int eA = 0, sA = 0, eB = 0, sB = 0;
    if (lane < deg)      { eA = g_eidx[s0 + lane];      sA = src[eA]; }
    if (lane + 32 < deg) { eB = g_eidx[s0 + lane + 32]; sB = src[eB]; }

    float m[8], myS0[8], myS1[8];
#pragma unroll
    for (int h = 0; h < 8; h++) m[h] = -1e30f;

    int dmain = deg < 64 ? deg : 64;
    for (int j = 0; j < dmain; j++) {
        int s = (j < 32) ? __shfl_sync(0xffffffffu, sA, j)
                         : __shfl_sync(0xffffffffu, sB, j - 32);
        const __half2* Pr = PQ + (size_t)s * 512;
        float sc[8];
#pragma unroll
        for (int p = 0; p < 2; p++) {
            float v = 0.f;
#pragma unroll
            for (int jj = 0; jj < 4; jj++) {
                float2 pv = __half22float2(Pr[pidx[p][jj]]);
                float z0 = pv.x + qb[p][jj].x; z0 = z0 > 0.f ? z0 : 0.01f * z0;
                float z1 = pv.y + qb[p][jj].y; z1 = z1 > 0.f ? z1 : 0.01f * z1;
                v = fmaf(z0, aw2[p][jj].x, fmaf(z1, aw2[p][jj].y, v));
            }
            v += __shfl_xor_sync(0xffffffffu, v, 4);
            v += __shfl_xor_sync(0xffffffffu, v, 2);
            v += __shfl_xor_sync(0xffffffffu, v, 1);
#pragma unroll
            for (int k = 0; k < 4; k++)
                sc[p * 4 + k] = __shfl_sync(0xffffffffu, v, k * 8);
        }
#pragma unroll
        for (int h = 0; h < 8; h++) m[h] = fmaxf(m[h], sc[h]);
        if (j < 32) {
            if (lane == j) {
#pragma unroll
                for (int h = 0; h < 8; h++) myS0[h] = sc[h];
            }
        } else if (lane == j - 32) {
#pragma unroll
            for (int h = 0; h < 8; h++) myS1[h] = sc[h];
        }
    }
    // rare tail deg > 64: same scoring, lane-0 spill to g_score
    for (int j = 64; j < deg; j++) {
        int e = g_eidx[s0 + j];
        int s = src[e];
        const __half2* Pr = PQ + (size_t)s * 512;
        float sc[8];
#pragma unroll
        for (int p = 0; p < 2; p++) {
            float v = 0.f;
#pragma unroll
            for (int jj = 0; jj < 4; jj++) {
                float2 pv = __half22float2(Pr[pidx[p][jj]]);
                float z0 = pv.x + qb[p][jj].x; z0 = z0 > 0.f ? z0 : 0.01f * z0;
                float z1 = pv.y + qb[p][jj].y; z1 = z1 > 0.f ? z1 : 0.01f * z1;
                v = fmaf(z0, aw2[p][jj].x, fmaf(z1, aw2[p][jj].y, v));
            }
            v += __shfl_xor_sync(0xffffffffu, v, 4);
            v += __shfl_xor_sync(0xffffffffu, v, 2);
            v += __shfl_xor_sync(0xffffffffu, v, 1);
#pragma unroll
            for (int k = 0; k < 4; k++)
                sc[p * 4 + k] = __shfl_sync(0xffffffffu, v, k * 8);
        }
#pragma unroll
        for (int h = 0; h < 8; h++) m[h] = fmaxf(m[h], sc[h]);
        if (lane == 0) {
#pragma unroll
            for (int h = 0; h < 8; h++) g_score[e * 8 + h] = sc[h];
        }
    }

    float ex0[8], ex1[8], dsum[8];
#pragma unroll
    for (int h = 0; h < 8; h++) dsum[h] = 0.f;
    if (lane < deg) {
#pragma unroll
        for (int h = 0; h < 8; h++) { ex0[h] = __expf(myS0[h] - m[h]); dsum[h] += ex0[h]; }
    }
    if (lane + 32 < deg) {
#pragma unroll
        for (int h = 0; h < 8; h++) { ex1[h] = __expf(myS1[h] - m[h]); dsum[h] += ex1[h]; }
    }
    if (lane == 0) {
        for (int j = 64; j < deg; j++) {
            int e = g_eidx[s0 + j];
#pragma unroll
            for (int h = 0; h < 8; h++) dsum[h] += __expf(g_score[e * 8 + h] - m[h]);
        }
    }
#pragma unroll
    for (int h = 0; h < 8; h++)
#pragma unroll
        for (int o = 16; o; o >>= 1)
            dsum[h] += __shfl_xor_sync(0xffffffffu, dsum[h], o);

    float inv[8];
#pragma unroll
    for (int h = 0; h < 8; h++) inv[h] = 1.f / dsum[h];

    if (lane < deg) {
        *(float4*)&g_score[eA * 8] =
            make_float4(ex0[0] * inv[0], ex0[1] * inv[1], ex0[2] * inv[2], ex0[3] * inv[3]);
        *(float4*)&g_score[eA * 8 + 4] =
            make_float4(ex0[4] * inv[4], ex0[5] * inv[5], ex0[6] * inv[6], ex0[7] * inv[7]);
    }
    if (lane + 32 < deg) {
        *(float4*)&g_score[eB * 8] =
            make_float4(ex1[0] * inv[0], ex1[1] * inv[1], ex1[2] * inv[2], ex1[3] * inv[3]);
        *(float4*)&g_score[eB * 8 + 4] =
            make_float4(ex1[4] * inv[4], ex1[5] * inv[5], ex1[6] * inv[6], ex1[7] * inv[7]);
    }
    if (lane == 0) {
        for (int j = 64; j < deg; j++) {
            int e = g_eidx[s0 + j];
#pragma unroll
            for (int h = 0; h < 8; h++)
                g_score[e * 8 + h] = __expf(g_score[e * 8 + h] - m[h]) * inv[h];
        }
    }
}

// ---------------- weighted aggregation (+ optional fp16 plane) ---------------
__global__ void agg_k(const float* __restrict__ hin, const int* __restrict__ src,
                      float* __restrict__ hout, __half* __restrict__ o1) {
    int node = blockIdx.x;
    int t = threadIdx.x;
    int lane = t & 31;
    int hd = t >> 4;
    int s0 = g_start[node], s1 = g_start[node + 1];
    int deg = s1 - s0;

    int eA = 0, snA = 0, eB = 0, snB = 0;
    if (lane < deg)      { eA = g_eidx[s0 + lane];      snA = src[eA]; }
    if (lane + 32 < deg) { eB = g_eidx[s0 + lane + 32]; snB = src[eB]; }

    float4 acc = make_float4(0.f, 0.f, 0.f, 0.f);
    int dmain = deg < 64 ? deg : 64;
    for (int i = 0; i < dmain; i++) {
        int e, sn;
        if (i < 32) {
            e  = __shfl_sync(0xffffffffu, eA, i);
            sn = __shfl_sync(0xffffffffu, snA, i);
        } else {
            e  = __shfl_sync(0xffffffffu, eB, i - 32);
            sn = __shfl_sync(0xffffffffu, snB, i - 32);
        }
        float a = g_score[e * 8 + hd];
        float4 v = ((const float4*)hin)[(size_t)sn * 128 + t];
        acc.x = fmaf(a, v.x, acc.x);
        acc.y = fmaf(a, v.y, acc.y);
        acc.z = fmaf(a, v.z, acc.z);
        acc.w = fmaf(a, v.w, acc.w);
    }
    for (int i = 64; i < deg; i++) {
        int e = g_eidx[s0 + i];
        int sn = src[e];
        float a = g_score[e * 8 + hd];
        float4 v = ((const float4*)hin)[(size_t)sn * 128 + t];
        acc.x = fmaf(a, v.x, acc.x);
        acc.y = fmaf(a, v.y, acc.y);
        acc.z = fmaf(a, v.z, acc.z);
        acc.w = fmaf(a, v.w, acc.w);
    }
    ((float4*)hout)[(size_t)node * 128 + t] = acc;
    if (o1) {
        size_t o = (size_t)node * 512 + t * 4;
        *(__half2*)&o1[o]     = __floats2half2_rn(acc.x, acc.y);
        *(__half2*)&o1[o + 2] = __floats2half2_rn(acc.z, acc.w);
    }
}

// ---------------- launch ----------------------------------------------------
extern "C" void kernel_launch(void* const* d_in, const int* in_sizes, int n_in,
                              void* d_out, int out_size) {
    (void)in_sizes; (void)n_in; (void)out_size;
    const float* x   = (const float*)d_in[0];
    const int*   src = (const int*)d_in[2];
    const int*   dst = (const int*)d_in[3];
    const float* Wn  = (const float*)d_in[4];
    const float* bn  = (const float*)d_in[5];
    const float* Wa  = (const float*)d_in[8];
    const float* ba  = (const float*)d_in[9];
    const float* aw  = (const float*)d_in[10];
    float* out = (float*)d_out;

    const int SMEM4 = 2 * 4 * PLANE_B;   // 81920  (h0: 3-term, BK=32)
    cudaFuncSetAttribute(gemm_h0_k, cudaFuncAttributeMaxDynamicSharedMemorySize, SMEM4);
    cudaFuncSetAttribute(gemm_pq_k, cudaFuncAttributeMaxDynamicSharedMemorySize, SMEM2);

    float *p_h, *p_h2;
    __half *p_PQh, *p_x1, *p_x2, *p_hA1, *p_WnT1, *p_WnT2, *p_Wc1;
    cudaGetSymbolAddress((void**)&p_h,    g_h);
    cudaGetSymbolAddress((void**)&p_h2,   g_h2);
    cudaGetSymbolAddress((void**)&p_PQh,  g_PQh);
    cudaGetSymbolAddress((void**)&p_x1,   g_x1);
    cudaGetSymbolAddress((void**)&p_x2,   g_x2);
    cudaGetSymbolAddress((void**)&p_hA1,  g_hA1);
    cudaGetSymbolAddress((void**)&p_WnT1, g_WnT1);
    cudaGetSymbolAddress((void**)&p_WnT2, g_WnT2);
    cudaGetSymbolAddress((void**)&p_Wc1,  g_Wc1);

    dim3 g_h0(HC / BN, NN / BM);       // (4, 256)
    dim3 g_pq(NOUT2 / BN, NN / BM);    // (8, 256)

    // prep, then h0 GEMM early so the profiler window lands on a GEMM
    split_x_k<<<NN * KPAD / 256, 256>>>(x);
    pack_wn_k<<<HC * KPAD / 256, 256>>>(Wn);
    pack_wa_k<<<NOUT2 * HC / 256, 256>>>(Wa);

    // h0 = x @ Wn + bn : fp32 h + fp16 h plane (3-term compensated)
    gemm_h0_k<<<g_h0, 256, SMEM4>>>(p_x1, p_x2, p_WnT1, p_WnT2, bn,
                                    p_h, p_hA1, KPAD, HC);

    // CSR build
    zero_k<<<NN / 256, 256>>>();
    count_k<<<NE / 256, 256>>>(dst);
    scan_k<<<1, 1024>>>();
    scatter_k<<<NE / 256, 256>>>(dst);

    // ---- layer 1 ----
    gemm_pq_k<<<g_pq, 256, SMEM2>>>(p_hA1, p_Wc1, p_PQh);
    fused_attn_k<<<NN / 8, 256>>>((const __half2*)p_PQh, ba, aw, src);
    agg_k<<<NN, 128>>>(p_h, src, p_h2, p_hA1);

    // ---- layer 2 ----
    gemm_pq_k<<<g_pq, 256, SMEM2>>>(p_hA1, p_Wc1, p_PQh);
    fused_attn_k<<<NN / 8, 256>>>((const __half2*)p_PQh, ba, aw, src);
    agg_k<<<NN, 128>>>(p_h2, src, out, nullptr);
}